// round 5
// baseline (speedup 1.0000x reference)
#include <cuda_runtime.h>
#include <cuda_bf16.h>
#include <stdint.h>

#define NN 50000
#define EE 800000
#define DIMK 64
#define BN_EPS 1e-5f
#define L2_EPS 1e-12f

// ---- scratch (device globals; no allocation allowed) ----
__device__ __align__(16) float g_h[NN * DIMK];     // h = x @ W
__device__ __align__(16) float g_acc[NN * DIMK];   // aggregated rows
__device__ float g_dinv[NN];
__device__ int   g_cnt[NN];
__device__ int   g_cursor[NN];
__device__ int   g_rowptr[NN + 1];
__device__ int2  g_edge[EE];                       // (src, dst) int32
__device__ int2  g_csr[EE];                        // (src, norm-as-bits) by dst
__device__ float g_sum[DIMK];
__device__ float g_sumsq[DIMK];
__device__ int   g_is32;

// ---- 0) probe dtype + zero counters/stats ----
__global__ void k_init(const unsigned int* __restrict__ ei32, int n) {
    int i = blockIdx.x * blockDim.x + threadIdx.x;
    if (i < n) { g_cnt[i] = 0; g_cursor[i] = 0; }
    if (i < DIMK) { g_sum[i] = 0.0f; g_sumsq[i] = 0.0f; }
    if (blockIdx.x == 0) {
        int tid = threadIdx.x;
        unsigned int acc = 0;
        for (int j = tid; j < 2048; j += 256) acc |= ei32[2 * j + 1];
        __shared__ unsigned int sh[256];
        sh[tid] = acc;
        __syncthreads();
        for (int s = 128; s > 0; s >>= 1) {
            if (tid < s) sh[tid] |= sh[tid + s];
            __syncthreads();
        }
        if (tid == 0) g_is32 = (sh[0] != 0) ? 1 : 0;
    }
}

__device__ __forceinline__ int load_idx(const void* ei, long long pos, int is32) {
    if (is32) return ((const int*)ei)[pos];
    return (int)((const long long*)ei)[pos];
}

// ---- 1) count per-dst + stage indices as int32 pairs ----
__global__ void k_count(const void* __restrict__ ei, int E) {
    int e = blockIdx.x * blockDim.x + threadIdx.x;
    if (e >= E) return;
    int is32 = g_is32;
    int src = load_idx(ei, e, is32);
    int dst = load_idx(ei, (long long)E + e, is32);
    g_edge[e] = make_int2(src, dst);
    atomicAdd(&g_cnt[dst], 1);
}

// ---- 2) exclusive scan of counts (single block) + dinv = rsqrt(cnt+1) ----
__global__ void k_scan(int n, int E) {
    __shared__ int partial[1024];
    int t = threadIdx.x;
    const int chunk = (n + 1023) / 1024;
    int start = t * chunk;
    int end = start + chunk; if (end > n) end = n; if (start > n) start = n;
    int s = 0;
    for (int i = start; i < end; i++) s += g_cnt[i];
    partial[t] = s;
    __syncthreads();
    for (int off = 1; off < 1024; off <<= 1) {
        int tmp = (t >= off) ? partial[t - off] : 0;
        __syncthreads();
        partial[t] += tmp;
        __syncthreads();
    }
    int run = partial[t] - s;   // exclusive
    for (int i = start; i < end; i++) {
        int c = g_cnt[i];
        g_rowptr[i] = run;
        run += c;
        g_dinv[i] = rsqrtf((float)(c + 1));
    }
    if (t == 1023) g_rowptr[n] = E;
}

// ---- 3) fill CSR: (src, norm) grouped by dst ----
__global__ void k_fill(int E) {
    int e = blockIdx.x * blockDim.x + threadIdx.x;
    if (e >= E) return;
    int2 sd = g_edge[e];
    float norm = g_dinv[sd.x] * g_dinv[sd.y];
    int pos = g_rowptr[sd.y] + atomicAdd(&g_cursor[sd.y], 1);
    g_csr[pos] = make_int2(sd.x, __float_as_int(norm));
}

// ---- 4) GEMM h = x@W (register-tiled 4x4) ----
__global__ void k_gemm(const float* __restrict__ x, const float* __restrict__ W, int n) {
    __shared__ float Wsh[DIMK][68];
    __shared__ float xsh[DIMK][68];
    int tid = threadIdx.x;
    int row0 = blockIdx.x * 64;

    for (int i = tid; i < 1024; i += 256) {
        int r  = i >> 4;
        int c4 = (i & 15) << 2;
        float4 v = ((const float4*)W)[i];
        *(float4*)&Wsh[r][c4] = v;
    }
    for (int i = tid; i < 1024; i += 256) {
        int r  = i >> 4;
        int c4 = (i & 15) << 2;
        int gr = row0 + r;
        float4 v = (gr < n) ? ((const float4*)x)[(size_t)gr * 16 + (i & 15)]
                            : make_float4(0.f, 0.f, 0.f, 0.f);
        *(float4*)&xsh[r][c4] = v;
    }
    __syncthreads();

    int tr = tid >> 4;
    int tc = (tid & 15) << 2;
    float acc[4][4] = {};
    #pragma unroll
    for (int k = 0; k < DIMK; k++) {
        float4 wv = *(const float4*)&Wsh[k][tc];
        float xv[4];
        #pragma unroll
        for (int i = 0; i < 4; i++) xv[i] = xsh[i * 16 + tr][k];
        #pragma unroll
        for (int i = 0; i < 4; i++) {
            acc[i][0] = fmaf(xv[i], wv.x, acc[i][0]);
            acc[i][1] = fmaf(xv[i], wv.y, acc[i][1]);
            acc[i][2] = fmaf(xv[i], wv.z, acc[i][2]);
            acc[i][3] = fmaf(xv[i], wv.w, acc[i][3]);
        }
    }
    #pragma unroll
    for (int i = 0; i < 4; i++) {
        int r = row0 + i * 16 + tr;
        if (r >= n) continue;
        *(float4*)&g_h[(size_t)r * DIMK + tc] =
            make_float4(acc[i][0], acc[i][1], acc[i][2], acc[i][3]);
    }
}

// ---- 5) aggregate: warp per dst (persistent), self-loop + edges + BN stats ----
__global__ void k_agg(int n) {
    __shared__ float shs[8][DIMK];
    __shared__ float shq[8][DIMK];
    int lane = threadIdx.x & 31;
    int w    = threadIdx.x >> 5;            // 0..7
    int warpGlobal = blockIdx.x * 8 + w;
    int warpStride = gridDim.x * 8;

    float s0 = 0.f, q0 = 0.f, s1 = 0.f, q1 = 0.f;

    for (int dst = warpGlobal; dst < n; dst += warpStride) {
        float dv = g_dinv[dst];
        float sl = dv * dv;
        size_t hb = (size_t)dst * DIMK;
        float a0 = g_h[hb + lane] * sl;
        float a1 = g_h[hb + lane + 32] * sl;
        int p  = g_rowptr[dst];
        int p1 = g_rowptr[dst + 1];
        for (; p + 1 < p1; p += 2) {
            int2 e0 = g_csr[p];
            int2 e1 = g_csr[p + 1];
            float n0 = __int_as_float(e0.y);
            float n1 = __int_as_float(e1.y);
            size_t b0 = (size_t)e0.x * DIMK;
            size_t b1 = (size_t)e1.x * DIMK;
            float h00 = g_h[b0 + lane],      h01 = g_h[b0 + lane + 32];
            float h10 = g_h[b1 + lane],      h11 = g_h[b1 + lane + 32];
            a0 = fmaf(n0, h00, a0); a1 = fmaf(n0, h01, a1);
            a0 = fmaf(n1, h10, a0); a1 = fmaf(n1, h11, a1);
        }
        if (p < p1) {
            int2 e0 = g_csr[p];
            float n0 = __int_as_float(e0.y);
            size_t b0 = (size_t)e0.x * DIMK;
            a0 = fmaf(n0, g_h[b0 + lane], a0);
            a1 = fmaf(n0, g_h[b0 + lane + 32], a1);
        }
        g_acc[hb + lane]      = a0;
        g_acc[hb + lane + 32] = a1;
        s0 += a0; q0 += a0 * a0;
        s1 += a1; q1 += a1 * a1;
    }

    shs[w][lane] = s0; shs[w][lane + 32] = s1;
    shq[w][lane] = q0; shq[w][lane + 32] = q1;
    __syncthreads();
    if (threadIdx.x < DIMK) {
        float ts = 0.f, tq = 0.f;
        #pragma unroll
        for (int i = 0; i < 8; i++) { ts += shs[i][threadIdx.x]; tq += shq[i][threadIdx.x]; }
        atomicAdd(&g_sum[threadIdx.x], ts);
        atomicAdd(&g_sumsq[threadIdx.x], tq);
    }
}

// ---- 6) finalize: BN (b cancels) -> ReLU -> L2 row-normalize -> out ----
__global__ void k_final(const float* __restrict__ gamma, const float* __restrict__ beta,
                        float* __restrict__ out, int n) {
    int warp = (blockIdx.x * blockDim.x + threadIdx.x) >> 5;
    int lane = threadIdx.x & 31;
    if (warp >= n) return;
    const float invN = 1.0f / (float)n;

    int c0 = lane, c1 = lane + 32;
    float m0 = g_sum[c0] * invN, m1 = g_sum[c1] * invN;
    float v0 = g_sumsq[c0] * invN - m0 * m0;
    float v1 = g_sumsq[c1] * invN - m1 * m1;
    float sc0 = rsqrtf(v0 + BN_EPS) * gamma[c0];
    float sc1 = rsqrtf(v1 + BN_EPS) * gamma[c1];

    size_t base = (size_t)warp * DIMK;
    float a0 = g_acc[base + c0];
    float a1 = g_acc[base + c1];
    float y0 = fmaf(a0 - m0, sc0, beta[c0]);
    float y1 = fmaf(a1 - m1, sc1, beta[c1]);
    y0 = fmaxf(y0, 0.0f);
    y1 = fmaxf(y1, 0.0f);

    float ss = y0 * y0 + y1 * y1;
    #pragma unroll
    for (int o = 16; o > 0; o >>= 1)
        ss += __shfl_xor_sync(0xffffffffu, ss, o);
    float nrm = sqrtf(ss);
    float inv = 1.0f / fmaxf(nrm, L2_EPS);
    out[base + c0] = y0 * inv;
    out[base + c1] = y1 * inv;
}

extern "C" void kernel_launch(void* const* d_in, const int* in_sizes, int n_in,
                              void* d_out, int out_size) {
    const float* x     = (const float*)d_in[0];
    const void*  ei    = d_in[1];                 // int32 or int64, probed at runtime
    const float* W     = (const float*)d_in[2];
    // const float* b  = (const float*)d_in[3];   // cancels exactly in BN
    const float* gamma = (const float*)d_in[4];
    const float* beta  = (const float*)d_in[5];
    float* out = (float*)d_out;

    int n = in_sizes[0] / DIMK;       // 50000
    int E = in_sizes[1] / 2;          // 800000

    k_init <<<(n + 255) / 256, 256>>>((const unsigned int*)ei, n);
    k_count<<<(E + 255) / 256, 256>>>(ei, E);
    k_scan <<<1, 1024>>>(n, E);
    k_fill <<<(E + 255) / 256, 256>>>(E);
    k_gemm <<<(n + 63) / 64, 256>>>(x, W, n);
    k_agg  <<<1024, 256>>>(n);
    k_final<<<(n + 7) / 8, 256>>>(gamma, beta, out, n);
}

// round 6
// speedup vs baseline: 1.6278x; 1.6278x over previous
#include <cuda_runtime.h>
#include <cuda_bf16.h>
#include <stdint.h>

#define NN 50000
#define DIMK 64
#define BN_EPS 1e-5f
#define L2_EPS 1e-12f

// ---- scratch (device globals; no allocation allowed) ----
__device__ __align__(16) float g_h[NN * DIMK];     // h = x @ W
__device__ __align__(16) float g_acc[NN * DIMK];   // self-loop + edge accumulator
__device__ int   g_degi[NN];                       // edge count per dst (excl. self)
__device__ float g_dinv[NN];
__device__ float g_sum[DIMK];
__device__ float g_sumsq[DIMK];
__device__ int   g_is32;                           // 1 if edge_index is int32

// ---- 0) fused: dtype probe + zero degree counters + zero BN stats ----
__global__ void k_init(const unsigned int* __restrict__ ei32, int n) {
    int i = blockIdx.x * blockDim.x + threadIdx.x;
    if (i < n) g_degi[i] = 0;
    if (i < DIMK) { g_sum[i] = 0.0f; g_sumsq[i] = 0.0f; }
    if (blockIdx.x == 0) {
        int tid = threadIdx.x;
        unsigned int acc = 0;
        for (int j = tid; j < 2048; j += 256) acc |= ei32[2 * j + 1];
        __shared__ unsigned int sh[256];
        sh[tid] = acc;
        __syncthreads();
        for (int s = 128; s > 0; s >>= 1) {
            if (tid < s) sh[tid] |= sh[tid + s];
            __syncthreads();
        }
        if (tid == 0) g_is32 = (sh[0] != 0) ? 1 : 0;
    }
}

__device__ __forceinline__ int load_idx(const void* ei, long long pos, int is32) {
    if (is32) return ((const int*)ei)[pos];
    return (int)((const long long*)ei)[pos];
}

// ---- 1) degree: int atomicAdd 1 per edge at dst ----
__global__ void k_deg(const void* __restrict__ ei, int E) {
    int e = blockIdx.x * blockDim.x + threadIdx.x;
    if (e >= E) return;
    int dst = load_idx(ei, (long long)E + e, g_is32);
    atomicAdd(&g_degi[dst], 1);
}

// ---- 2) GEMM h = x@W (register-tiled 4x4) + dinv + self-loop into acc ----
// block 256 threads, 64-row x 64-col tile; thread computes 4 rows x 4 cols.
__global__ void k_gemm(const float* __restrict__ x, const float* __restrict__ W, int n) {
    __shared__ float Wsh[DIMK][68];
    __shared__ float xsh[DIMK][68];
    int tid = threadIdx.x;
    int row0 = blockIdx.x * 64;

    for (int i = tid; i < 1024; i += 256) {
        int r  = i >> 4;
        int c4 = (i & 15) << 2;
        *(float4*)&Wsh[r][c4] = ((const float4*)W)[i];
    }
    for (int i = tid; i < 1024; i += 256) {
        int r  = i >> 4;
        int c4 = (i & 15) << 2;
        int gr = row0 + r;
        float4 v = (gr < n) ? ((const float4*)x)[(size_t)gr * 16 + (i & 15)]
                            : make_float4(0.f, 0.f, 0.f, 0.f);
        *(float4*)&xsh[r][c4] = v;
    }
    __syncthreads();

    int tr = tid >> 4;            // 0..15
    int tc = (tid & 15) << 2;     // col base
    float acc[4][4] = {};
    #pragma unroll
    for (int k = 0; k < DIMK; k++) {
        float4 wv = *(const float4*)&Wsh[k][tc];
        float xv[4];
        #pragma unroll
        for (int i = 0; i < 4; i++) xv[i] = xsh[i * 16 + tr][k];
        #pragma unroll
        for (int i = 0; i < 4; i++) {
            acc[i][0] = fmaf(xv[i], wv.x, acc[i][0]);
            acc[i][1] = fmaf(xv[i], wv.y, acc[i][1]);
            acc[i][2] = fmaf(xv[i], wv.z, acc[i][2]);
            acc[i][3] = fmaf(xv[i], wv.w, acc[i][3]);
        }
    }
    #pragma unroll
    for (int i = 0; i < 4; i++) {
        int r = row0 + i * 16 + tr;
        if (r >= n) continue;
        float dv = rsqrtf((float)(1 + g_degi[r]));
        if (tc == 0) g_dinv[r] = dv;
        float s = dv * dv;
        size_t o = (size_t)r * DIMK + tc;
        float4 hv = make_float4(acc[i][0], acc[i][1], acc[i][2], acc[i][3]);
        *(float4*)&g_h[o] = hv;
        *(float4*)&g_acc[o] = make_float4(hv.x * s, hv.y * s, hv.z * s, hv.w * s);
    }
}

// ---- 3) edge scatter: acc[dst] += dinv[src]*dinv[dst] * h[src] ----
// one thread per (edge, float4 group): E*16 threads, 1 red.v4 each.
// Index/dinv loads are identical across the 16 threads of an edge -> L1 broadcast.
__global__ void k_scatter(const void* __restrict__ ei, int E) {
    long long gid = (long long)blockIdx.x * blockDim.x + threadIdx.x;
    if (gid >= (long long)E * 16) return;
    int e = (int)(gid >> 4);
    int g = (int)(gid & 15);
    int is32 = g_is32;
    int src = load_idx(ei, e, is32);
    int dst = load_idx(ei, (long long)E + e, is32);
    float norm = g_dinv[src] * g_dinv[dst];
    const float4 hv = *reinterpret_cast<const float4*>(&g_h[(size_t)src * DIMK + g * 4]);
    float vx = hv.x * norm, vy = hv.y * norm, vz = hv.z * norm, vw = hv.w * norm;
    float* addr = &g_acc[(size_t)dst * DIMK + g * 4];
    asm volatile("red.global.add.v4.f32 [%0], {%1, %2, %3, %4};"
                 :: "l"(addr), "f"(vx), "f"(vy), "f"(vz), "f"(vw) : "memory");
}

// ---- 4) BN column stats: per-block partial sums -> atomicAdd ----
__global__ void k_stats(int n) {
    int tid = threadIdx.x;
    int col = tid & 63;
    int rg  = tid >> 6;
    float s = 0.0f, s2 = 0.0f;
    for (int r = blockIdx.x * 4 + rg; r < n; r += gridDim.x * 4) {
        float v = g_acc[(size_t)r * DIMK + col];
        s += v; s2 += v * v;
    }
    __shared__ float sh[4][DIMK], sh2[4][DIMK];
    sh[rg][col] = s; sh2[rg][col] = s2;
    __syncthreads();
    if (rg == 0) {
        float ts  = sh[0][col] + sh[1][col] + sh[2][col] + sh[3][col];
        float ts2 = sh2[0][col] + sh2[1][col] + sh2[2][col] + sh2[3][col];
        atomicAdd(&g_sum[col], ts);
        atomicAdd(&g_sumsq[col], ts2);
    }
}

// ---- 5) finalize: BN (b cancels) -> ReLU -> L2 row-normalize -> out ----
__global__ void k_final(const float* __restrict__ gamma, const float* __restrict__ beta,
                        float* __restrict__ out, int n) {
    int warp = (blockIdx.x * blockDim.x + threadIdx.x) >> 5;
    int lane = threadIdx.x & 31;
    if (warp >= n) return;
    const float invN = 1.0f / (float)n;

    int c0 = lane, c1 = lane + 32;
    float m0 = g_sum[c0] * invN, m1 = g_sum[c1] * invN;
    float v0 = g_sumsq[c0] * invN - m0 * m0;
    float v1 = g_sumsq[c1] * invN - m1 * m1;
    float sc0 = rsqrtf(v0 + BN_EPS) * gamma[c0];
    float sc1 = rsqrtf(v1 + BN_EPS) * gamma[c1];

    size_t base = (size_t)warp * DIMK;
    float a0 = g_acc[base + c0];
    float a1 = g_acc[base + c1];
    float y0 = fmaf(a0 - m0, sc0, beta[c0]);
    float y1 = fmaf(a1 - m1, sc1, beta[c1]);
    y0 = fmaxf(y0, 0.0f);
    y1 = fmaxf(y1, 0.0f);

    float ss = y0 * y0 + y1 * y1;
    #pragma unroll
    for (int o = 16; o > 0; o >>= 1)
        ss += __shfl_xor_sync(0xffffffffu, ss, o);
    float nrm = sqrtf(ss);
    float inv = 1.0f / fmaxf(nrm, L2_EPS);
    out[base + c0] = y0 * inv;
    out[base + c1] = y1 * inv;
}

extern "C" void kernel_launch(void* const* d_in, const int* in_sizes, int n_in,
                              void* d_out, int out_size) {
    const float* x     = (const float*)d_in[0];
    const void*  ei    = d_in[1];                 // int32 or int64, probed at runtime
    const float* W     = (const float*)d_in[2];
    // const float* b  = (const float*)d_in[3];   // cancels exactly in BN
    const float* gamma = (const float*)d_in[4];
    const float* beta  = (const float*)d_in[5];
    float* out = (float*)d_out;

    int n = in_sizes[0] / DIMK;       // 50000
    int E = in_sizes[1] / 2;          // 800000

    k_init   <<<(n + 255) / 256, 256>>>((const unsigned int*)ei, n);
    k_deg    <<<(E + 255) / 256, 256>>>(ei, E);
    k_gemm   <<<(n + 63) / 64, 256>>>(x, W, n);
    {
        long long total = (long long)E * 16;
        int grid = (int)((total + 255) / 256);
        k_scatter<<<grid, 256>>>(ei, E);
    }
    k_stats  <<<256, 256>>>(n);
    k_final  <<<(n + 7) / 8, 256>>>(gamma, beta, out, n);
}